// round 4
// baseline (speedup 1.0000x reference)
#include <cuda_runtime.h>
#include <math.h>

#define NPTS   8192
#define BATCH  2
#define TI     128                 // rows per block tile
#define TJ     512                 // cols per block tile
#define IT     (NPTS / TI)         // 64 row tiles
#define JT     (NPTS / TJ)         // 16 col tiles
#define THREADS 256
#define IR     8                   // rows per thread (ty: 16 groups)
#define ICP    16                  // col-pairs per thread (tx: 16 groups, 32 cols)

// Partials: each written by exactly one block (no atomics, deterministic).
__device__ float g_rowpart[JT][BATCH * NPTS];   // min over each 512-col tile, per gt row
__device__ float g_colpart[IT][BATCH * NPTS];   // min over each 128-row tile, per pred col
__device__ float g_bsum[64];

// ---- packed f32x2 helpers --------------------------------------------------
static __device__ __forceinline__ unsigned long long pack2(float lo, float hi) {
    unsigned long long r;
    asm("mov.b64 %0, {%1, %2};" : "=l"(r) : "f"(lo), "f"(hi));
    return r;
}
static __device__ __forceinline__ void unpack2(unsigned long long v, float& lo, float& hi) {
    asm("mov.b64 {%0, %1}, %2;" : "=f"(lo), "=f"(hi) : "l"(v));
}
static __device__ __forceinline__ unsigned long long fma2(
    unsigned long long a, unsigned long long b, unsigned long long c) {
    unsigned long long d;
    asm("fma.rn.f32x2 %0, %1, %2, %3;" : "=l"(d) : "l"(a), "l"(b), "l"(c));
    return d;
}
static __device__ __forceinline__ unsigned long long add2(
    unsigned long long a, unsigned long long b) {
    unsigned long long d;
    asm("add.rn.f32x2 %0, %1, %2;" : "=l"(d) : "l"(a), "l"(b));
    return d;
}

// Grid (IT, JT, BATCH). Tile: 128 gt-rows x 512 pred-cols.
// s_ij = g2_i + p2_j - 2<g_i,p_j>; row-min -> dist1 partial, col-min -> dist2 partial.
__global__ void __launch_bounds__(THREADS)
fused_kernel(const float* __restrict__ pred, const float* __restrict__ gt) {
    __shared__ float4 qrow[TI];           // (x, y, z, g2)            2 KB
    __shared__ float4 colA[TJ / 2];       // {-2x0,-2x1,-2y0,-2y1}    4 KB
    __shared__ float4 colB[TJ / 2];       // {-2z0,-2z1,  w0,  w1}    4 KB
    __shared__ float  colred[16][TJ];     // per-ty col mins (transposed idx) 32 KB

    int it = blockIdx.x, jt = blockIdx.y, b = blockIdx.z;
    int tid = threadIdx.x;

    for (int i = tid; i < TI; i += THREADS) {
        const float* g = gt + (long)(b * NPTS + it * TI + i) * 3;
        float x = g[0], y = g[1], z = g[2];
        qrow[i] = make_float4(x, y, z, x * x + y * y + z * z);
    }
    for (int p = tid; p < TJ / 2; p += THREADS) {
        const float* q = pred + (long)(b * NPTS + jt * TJ + 2 * p) * 3;
        float x0 = q[0], y0 = q[1], z0 = q[2];
        float x1 = q[3], y1 = q[4], z1 = q[5];
        colA[p] = make_float4(-2.f * x0, -2.f * x1, -2.f * y0, -2.f * y1);
        colB[p] = make_float4(-2.f * z0, -2.f * z1,
                              x0 * x0 + y0 * y0 + z0 * z0,
                              x1 * x1 + y1 * y1 + z1 * z1);
    }
    __syncthreads();

    int ty = tid >> 4, tx = tid & 15;

    unsigned long long qxd[IR], qyd[IR], qzd[IR], qwd[IR];
    float rowlo[IR], rowhi[IR];
#pragma unroll
    for (int r = 0; r < IR; r++) {
        float4 q = qrow[ty * IR + r];
        qxd[r] = pack2(q.x, q.x); qyd[r] = pack2(q.y, q.y);
        qzd[r] = pack2(q.z, q.z); qwd[r] = pack2(q.w, q.w);
        rowlo[r] = 3.4e38f; rowhi[r] = 3.4e38f;
    }

    const ulonglong2* cA = (const ulonglong2*)colA;
    const ulonglong2* cB = (const ulonglong2*)colB;
#pragma unroll 2
    for (int cp = 0; cp < ICP; cp++) {
        int p = tx * ICP + cp;
        ulonglong2 P0 = cA[p];   // {pack(-2x0,-2x1), pack(-2y0,-2y1)}
        ulonglong2 P1 = cB[p];   // {pack(-2z0,-2z1), pack( w0,  w1)}
        float clo = 3.4e38f, chi = 3.4e38f;
#pragma unroll
        for (int r = 0; r < IR; r++) {
            unsigned long long t =
                fma2(qxd[r], P0.x, fma2(qyd[r], P0.y, fma2(qzd[r], P1.x, P1.y)));
            unsigned long long s = add2(t, qwd[r]);
            float slo, shi; unpack2(s, slo, shi);
            rowlo[r] = fminf(rowlo[r], slo);
            rowhi[r] = fminf(rowhi[r], shi);
            clo = fminf(clo, slo);
            chi = fminf(chi, shi);
        }
        // Transposed layout: lane stride = 2 banks (2-way conflict max),
        // instead of colred[ty][2p] whose lane stride is 32 banks (32-way).
        colred[ty][cp * 32 + 2 * tx]     = clo;
        colred[ty][cp * 32 + 2 * tx + 1] = chi;
    }

    // Row mins: butterfly over the 16 tx lanes (xor masks stay in 16-lane half).
#pragma unroll
    for (int r = 0; r < IR; r++) {
        float v = fminf(rowlo[r], rowhi[r]);
        v = fminf(v, __shfl_xor_sync(0xffffffffu, v, 1));
        v = fminf(v, __shfl_xor_sync(0xffffffffu, v, 2));
        v = fminf(v, __shfl_xor_sync(0xffffffffu, v, 4));
        v = fminf(v, __shfl_xor_sync(0xffffffffu, v, 8));
        if (tx == 0)
            g_rowpart[jt][(b << 13) + it * TI + ty * IR + r] = v;
    }

    __syncthreads();
    // Col mins: reduce the 16 ty slices; invert the transposed index:
    // s = cp*32 + 2*tx + e  ->  column = 2*(tx*ICP + cp) + e
    for (int s = tid; s < TJ; s += THREADS) {
        float m = colred[0][s];
#pragma unroll
        for (int yy = 1; yy < 16; yy++) m = fminf(m, colred[yy][s]);
        int e   = s & 1;
        int txs = (s & 31) >> 1;
        int cps = s >> 5;
        int c   = 2 * (txs * ICP + cps) + e;
        g_colpart[it][(b << 13) + jt * TJ + c] = m;
    }
}

// 64 blocks x 256 threads = 16384 = BATCH*NPTS items; each thread does one
// gt-row min (dist1) and one pred-col min (dist2).
__global__ void __launch_bounds__(256)
reduce2_kernel() {
    int idx = blockIdx.x * 256 + threadIdx.x;   // b*8192 + point, < 16384
    float rm = g_rowpart[0][idx];
#pragma unroll
    for (int j = 1; j < JT; j++) rm = fminf(rm, g_rowpart[j][idx]);
    float cm = g_colpart[0][idx];
#pragma unroll
    for (int i = 1; i < IT; i++) cm = fminf(cm, g_colpart[i][idx]);
    float s = sqrtf(fmaxf(rm, 0.f)) + sqrtf(fmaxf(cm, 0.f));

    __shared__ float sb[256];
    sb[threadIdx.x] = s;
    __syncthreads();
    for (int off = 128; off > 0; off >>= 1) {
        if (threadIdx.x < off) sb[threadIdx.x] += sb[threadIdx.x + off];
        __syncthreads();
    }
    if (threadIdx.x == 0) g_bsum[blockIdx.x] = sb[0];
}

__global__ void __launch_bounds__(64)
reduce3_kernel(float* __restrict__ out) {
    __shared__ float sb[64];
    sb[threadIdx.x] = g_bsum[threadIdx.x];
    __syncthreads();
    for (int off = 32; off > 0; off >>= 1) {
        if (threadIdx.x < off) sb[threadIdx.x] += sb[threadIdx.x + off];
        __syncthreads();
    }
    if (threadIdx.x == 0) out[0] = sb[0] / (float)(BATCH * NPTS);
}

extern "C" void kernel_launch(void* const* d_in, const int* in_sizes, int n_in,
                              void* d_out, int out_size) {
    const float* pred = (const float*)d_in[0];
    const float* gt   = (const float*)d_in[1];
    float* out = (float*)d_out;

    dim3 grid(IT, JT, BATCH);
    fused_kernel<<<grid, THREADS>>>(pred, gt);
    reduce2_kernel<<<64, 256>>>();
    reduce3_kernel<<<1, 64>>>(out);
}

// round 5
// speedup vs baseline: 2.0066x; 2.0066x over previous
#include <cuda_runtime.h>
#include <math.h>

#define NPTS   8192
#define BATCH  2
#define TI     128                 // rows per block tile
#define TJ     512                 // cols per block tile
#define IT     (NPTS / TI)         // 64 row tiles
#define JT     (NPTS / TJ)         // 16 col tiles
#define THREADS 256
#define IR     8                   // rows per thread (ty: 16 groups)
#define ICP    16                  // col-pairs per thread (cp iterations)
#define CRP    (TJ + 8)            // colred row pitch (pad: warp halves differ bank)

// Partials: each written by exactly one block (no atomics, deterministic).
__device__ float g_rowpart[JT][BATCH * NPTS];   // min over each 512-col tile, per gt row
__device__ float g_colpart[IT][BATCH * NPTS];   // min over each 128-row tile, per pred col
__device__ float g_bsum[64];

// ---- packed f32x2 helpers --------------------------------------------------
static __device__ __forceinline__ unsigned long long pack2(float lo, float hi) {
    unsigned long long r;
    asm("mov.b64 %0, {%1, %2};" : "=l"(r) : "f"(lo), "f"(hi));
    return r;
}
static __device__ __forceinline__ void unpack2(unsigned long long v, float& lo, float& hi) {
    asm("mov.b64 {%0, %1}, %2;" : "=f"(lo), "=f"(hi) : "l"(v));
}
static __device__ __forceinline__ unsigned long long fma2(
    unsigned long long a, unsigned long long b, unsigned long long c) {
    unsigned long long d;
    asm("fma.rn.f32x2 %0, %1, %2, %3;" : "=l"(d) : "l"(a), "l"(b), "l"(c));
    return d;
}
static __device__ __forceinline__ unsigned long long add2(
    unsigned long long a, unsigned long long b) {
    unsigned long long d;
    asm("add.rn.f32x2 %0, %1, %2;" : "=l"(d) : "l"(a), "l"(b));
    return d;
}

// Grid (IT, JT, BATCH). Tile: 128 gt-rows x 512 pred-cols.
// s_ij = g2_i + p2_j - 2<g_i,p_j>; row-min -> dist1 partial, col-min -> dist2 partial.
__global__ void __launch_bounds__(THREADS)
fused_kernel(const float* __restrict__ pred, const float* __restrict__ gt) {
    __shared__ float4 qrow[TI];           // (x, y, z, g2)            2 KB
    __shared__ float4 colA[TJ / 2];       // {-2x0,-2x1,-2y0,-2y1}    4 KB
    __shared__ float4 colB[TJ / 2];       // {-2z0,-2z1,  w0,  w1}    4 KB
    __shared__ float  colred[16][CRP];    // per-ty col mins (padded) ~32.5 KB

    int it = blockIdx.x, jt = blockIdx.y, b = blockIdx.z;
    int tid = threadIdx.x;

    for (int i = tid; i < TI; i += THREADS) {
        const float* g = gt + (long)(b * NPTS + it * TI + i) * 3;
        float x = g[0], y = g[1], z = g[2];
        qrow[i] = make_float4(x, y, z, x * x + y * y + z * z);
    }
    for (int p = tid; p < TJ / 2; p += THREADS) {
        const float* q = pred + (long)(b * NPTS + jt * TJ + 2 * p) * 3;
        float x0 = q[0], y0 = q[1], z0 = q[2];
        float x1 = q[3], y1 = q[4], z1 = q[5];
        colA[p] = make_float4(-2.f * x0, -2.f * x1, -2.f * y0, -2.f * y1);
        colB[p] = make_float4(-2.f * z0, -2.f * z1,
                              x0 * x0 + y0 * y0 + z0 * z0,
                              x1 * x1 + y1 * y1 + z1 * z1);
    }
    __syncthreads();

    int ty = tid >> 4, tx = tid & 15;

    unsigned long long qxd[IR], qyd[IR], qzd[IR], qwd[IR];
    float rowlo[IR], rowhi[IR];
#pragma unroll
    for (int r = 0; r < IR; r++) {
        float4 q = qrow[ty * IR + r];
        qxd[r] = pack2(q.x, q.x); qyd[r] = pack2(q.y, q.y);
        qzd[r] = pack2(q.z, q.z); qwd[r] = pack2(q.w, q.w);
        rowlo[r] = 3.4e38f; rowhi[r] = 3.4e38f;
    }

    const ulonglong2* cA = (const ulonglong2*)colA;
    const ulonglong2* cB = (const ulonglong2*)colB;
#pragma unroll 2
    for (int cp = 0; cp < ICP; cp++) {
        // Conflict-free mapping: lanes (tx) read CONSECUTIVE 16B chunks;
        // the two ty-halves of the warp read identical addresses (broadcast).
        int p = cp * 16 + tx;
        ulonglong2 P0 = cA[p];   // {pack(-2x0,-2x1), pack(-2y0,-2y1)}
        ulonglong2 P1 = cB[p];   // {pack(-2z0,-2z1), pack( w0,  w1)}
        float clo = 3.4e38f, chi = 3.4e38f;
#pragma unroll
        for (int r = 0; r < IR; r++) {
            unsigned long long t =
                fma2(qxd[r], P0.x, fma2(qyd[r], P0.y, fma2(qzd[r], P1.x, P1.y)));
            unsigned long long s = add2(t, qwd[r]);
            float slo, shi; unpack2(s, slo, shi);
            rowlo[r] = fminf(rowlo[r], slo);
            rowhi[r] = fminf(rowhi[r], shi);
            clo = fminf(clo, slo);
            chi = fminf(chi, shi);
        }
        // Identity column mapping: pair p covers columns 2p, 2p+1.
        *(float2*)&colred[ty][2 * p] = make_float2(clo, chi);
    }

    // Row mins: butterfly over the 16 tx lanes (xor masks stay in 16-lane half).
#pragma unroll
    for (int r = 0; r < IR; r++) {
        float v = fminf(rowlo[r], rowhi[r]);
        v = fminf(v, __shfl_xor_sync(0xffffffffu, v, 1));
        v = fminf(v, __shfl_xor_sync(0xffffffffu, v, 2));
        v = fminf(v, __shfl_xor_sync(0xffffffffu, v, 4));
        v = fminf(v, __shfl_xor_sync(0xffffffffu, v, 8));
        if (tx == 0)
            g_rowpart[jt][(b << 13) + it * TI + ty * IR + r] = v;
    }

    __syncthreads();
    // Col mins: reduce the 16 ty slices; index s IS the tile column now.
    for (int s = tid; s < TJ; s += THREADS) {
        float m = colred[0][s];
#pragma unroll
        for (int yy = 1; yy < 16; yy++) m = fminf(m, colred[yy][s]);
        g_colpart[it][(b << 13) + jt * TJ + s] = m;
    }
}

// 64 blocks x 256 threads = 16384 = BATCH*NPTS items; each thread does one
// gt-row min (dist1) and one pred-col min (dist2).
__global__ void __launch_bounds__(256)
reduce2_kernel() {
    int idx = blockIdx.x * 256 + threadIdx.x;   // b*8192 + point, < 16384
    float rm = g_rowpart[0][idx];
#pragma unroll
    for (int j = 1; j < JT; j++) rm = fminf(rm, g_rowpart[j][idx]);
    float cm = g_colpart[0][idx];
#pragma unroll
    for (int i = 1; i < IT; i++) cm = fminf(cm, g_colpart[i][idx]);
    float s = sqrtf(fmaxf(rm, 0.f)) + sqrtf(fmaxf(cm, 0.f));

    __shared__ float sb[256];
    sb[threadIdx.x] = s;
    __syncthreads();
    for (int off = 128; off > 0; off >>= 1) {
        if (threadIdx.x < off) sb[threadIdx.x] += sb[threadIdx.x + off];
        __syncthreads();
    }
    if (threadIdx.x == 0) g_bsum[blockIdx.x] = sb[0];
}

__global__ void __launch_bounds__(64)
reduce3_kernel(float* __restrict__ out) {
    __shared__ float sb[64];
    sb[threadIdx.x] = g_bsum[threadIdx.x];
    __syncthreads();
    for (int off = 32; off > 0; off >>= 1) {
        if (threadIdx.x < off) sb[threadIdx.x] += sb[threadIdx.x + off];
        __syncthreads();
    }
    if (threadIdx.x == 0) out[0] = sb[0] / (float)(BATCH * NPTS);
}

extern "C" void kernel_launch(void* const* d_in, const int* in_sizes, int n_in,
                              void* d_out, int out_size) {
    const float* pred = (const float*)d_in[0];
    const float* gt   = (const float*)d_in[1];
    float* out = (float*)d_out;

    dim3 grid(IT, JT, BATCH);
    fused_kernel<<<grid, THREADS>>>(pred, gt);
    reduce2_kernel<<<64, 256>>>();
    reduce3_kernel<<<1, 64>>>(out);
}